// round 10
// baseline (speedup 1.0000x reference)
#include <cuda_runtime.h>
#include <cuda_bf16.h>

// ---------------- problem constants ----------------
#define BATCHN   4096
#define KIN      8
#define KOUTN    4
#define HN       128
#define G3N      384           // 3*H gates
#define PRE_LENN 64
#define FWD_LENN 128
#define BT       16            // batch rows per CTA
#define TPB      256
#define NCTA     (BATCHN/BT)   // 256
#define COLSN    (BATCHN*KIN)  // 32768
#define Y_STR    132           // padded stride for [BT][128] smem buffers
#define G_STR    388           // padded stride for [BT][384] smem buffers
#define W2_STR   260

// ---------------- device scratch (no allocations allowed) ----------------
__device__ float g_ys[(FWD_LENN + 1) * COLSN];  // spline knots  [129][B][8]
__device__ float g_M [(FWD_LENN + 1) * COLSN];  // spline 2nd derivs
__device__ float g_hn[BATCHN * HN];             // encoder final hidden
// reordered weights: idx = k4*(OPT*128) + j*128 + og ; value = W[(og*OPT+j)][4k4..4k4+3]
__device__ float4 g_Wcih_r[32 * 384];
__device__ float4 g_Wchh_r[32 * 384];
__device__ float4 g_Whh_r [32 * 384];
__device__ float4 g_W1_r  [32 * 256];

// ---------------- packed fp32x2 FMA (Blackwell FFMA2; PTX-only path) ----------
#define FMA2(d, a, b) asm("fma.rn.f32x2 %0, %1, %2, %0;" : "+l"(d) : "l"(a), "l"(b))

__device__ __forceinline__ float ull_sum(unsigned long long v) {
    float lo = __uint_as_float((unsigned)(v & 0xffffffffull));
    float hi = __uint_as_float((unsigned)(v >> 32));
    return lo + hi;
}

__device__ __forceinline__ float sigf(float x) { return 1.f / (1.f + __expf(-x)); }

// ---------------- core GEMM: Out[BT x (128*OPT)] = Xs[BT x 128] @ W^T -------
// TPB=256: bg = t&1 (2 batch sub-groups), og = t>>1 (128 output groups).
// Each thread: OPT outputs x 8 batch rows (b = bg + 2*i). K paired via f32x2.
// MODE 0: Out = sum + bias[o]; MODE 1: Out = tanh(sum)
template <int OPT, int MODE>
__device__ __forceinline__ void mm128(const float4* __restrict__ Wr,
                                      const float* __restrict__ Xs, int xs,
                                      float* __restrict__ Out, int os,
                                      const float* __restrict__ bias)
{
    const int t  = threadIdx.x;
    const int bg = t & 1;
    const int og = t >> 1;
    unsigned long long acc[OPT][8];
#pragma unroll
    for (int j = 0; j < OPT; j++)
#pragma unroll
        for (int i = 0; i < 8; i++) acc[j][i] = 0ull;

#pragma unroll 2
    for (int k4 = 0; k4 < 32; k4++) {
        const int k = k4 * 4;
        unsigned long long x01[8], x23[8];
#pragma unroll
        for (int i = 0; i < 8; i++) {
            ulonglong2 xv = *reinterpret_cast<const ulonglong2*>(Xs + (bg + 2 * i) * xs + k);
            x01[i] = xv.x;
            x23[i] = xv.y;
        }
        const float4* wrow = Wr + (size_t)k4 * (OPT * 128) + og;
#pragma unroll
        for (int j = 0; j < OPT; j++) {
            ulonglong2 wv = *reinterpret_cast<const ulonglong2*>(wrow + j * 128);
#pragma unroll
            for (int i = 0; i < 8; i++) {
                FMA2(acc[j][i], wv.x, x01[i]);
                FMA2(acc[j][i], wv.y, x23[i]);
            }
        }
    }
#pragma unroll
    for (int j = 0; j < OPT; j++) {
        int o = og * OPT + j;
#pragma unroll
        for (int i = 0; i < 8; i++) {
            int b = bg + 2 * i;
            float s = ull_sum(acc[j][i]);
            if (MODE == 0) Out[b * os + o] = s + bias[o];
            else           Out[b * os + o] = tanhf(s);
        }
    }
}

// ---------------- weight reorder prep ----------------
__global__ void reorder_kernel(const float* __restrict__ Wc_ih,
                               const float* __restrict__ Wc_hh,
                               const float* __restrict__ W_hh,
                               const float* __restrict__ W1)
{
    int idx = blockIdx.x * blockDim.x + threadIdx.x;
    if (idx < 32 * 384) {
        int k4 = idx / 384, r = idx % 384;
        int j = r >> 7, og = r & 127;
        int row = og * 3 + j;
        g_Wcih_r[idx] = *reinterpret_cast<const float4*>(Wc_ih + (size_t)row * HN + k4 * 4);
        g_Wchh_r[idx] = *reinterpret_cast<const float4*>(Wc_hh + (size_t)row * HN + k4 * 4);
        g_Whh_r [idx] = *reinterpret_cast<const float4*>(W_hh  + (size_t)row * HN + k4 * 4);
    }
    if (idx < 32 * 256) {
        int k4 = idx / 256, r = idx % 256;
        int j = r >> 7, og = r & 127;
        int row = og * 2 + j;
        g_W1_r[idx] = *reinterpret_cast<const float4*>(W1 + (size_t)row * HN + k4 * 4);
    }
}

// ---------------- spline prep ----------------
__global__ void fill_kernel(const float* __restrict__ pre_x, const float* __restrict__ fwd_x)
{
    int e = blockIdx.x * blockDim.x + threadIdx.x;
    if (e >= (FWD_LENN + 1) * COLSN) return;
    int i   = e >> 15;             // COLSN = 2^15
    int col = e & (COLSN - 1);
    g_ys[e] = (i == 0) ? pre_x[(size_t)(PRE_LENN - 1) * COLSN + col]
                       : fwd_x[(size_t)(i - 1) * COLSN + col];
}

// Thomas solve of (1,4,1) tridiagonal per column; M[0]=M[128]=0
__global__ void thomas_kernel()
{
    __shared__ float cp[FWD_LENN];
    int t = threadIdx.x;
    int col = blockIdx.x * blockDim.x + t;
    if (t == 0) {
        cp[0] = 0.25f;
        for (int i = 1; i < FWD_LENN - 1; i++) cp[i] = 1.f / (4.f - cp[i - 1]);
    }
    __syncthreads();
    const float rc = 6.0f / (0.1f * 0.1f);
    float y0 = g_ys[col];
    float y1 = g_ys[COLSN + col];
    float dp = 0.f;
    for (int j = 0; j < FWD_LENN - 1; j++) {          // 127 inner unknowns
        float y2 = g_ys[(size_t)(j + 2) * COLSN + col];
        float rhs = rc * (y0 - 2.f * y1 + y2);
        dp = (rhs - dp) * cp[j];
        g_M[(size_t)(j + 1) * COLSN + col] = dp;
        y0 = y1; y1 = y2;
    }
    float x = dp;                                     // M[127] final
    for (int j = FWD_LENN - 3; j >= 0; j--) {
        float dj = g_M[(size_t)(j + 1) * COLSN + col];
        x = dj - cp[j] * x;
        g_M[(size_t)(j + 1) * COLSN + col] = x;
    }
    g_M[col] = 0.f;
    g_M[(size_t)FWD_LENN * COLSN + col] = 0.f;
}

// ---------------- encoder GRU ----------------
struct EncS {
    float A [BT * G_STR];
    float GH[BT * G_STR];
    float h [BT * Y_STR];
    float ins[BT * 12];
    float bih[G3N];
    float bhh[G3N];
};

__global__ void __launch_bounds__(TPB, 2) enc_kernel(
    const float* __restrict__ pre_x, const float* __restrict__ pre_y,
    const float* __restrict__ W_ih,
    const float* __restrict__ b_ih, const float* __restrict__ b_hh)
{
    extern __shared__ char smraw[];
    EncS* s = reinterpret_cast<EncS*>(smraw);
    const int t  = threadIdx.x;
    const int b0 = blockIdx.x * BT;

    for (int idx = t; idx < G3N; idx += TPB) { s->bih[idx] = b_ih[idx]; s->bhh[idx] = b_hh[idx]; }
#pragma unroll
    for (int ii = 0; ii < (BT * HN) / TPB; ii++) {
        int e = t + TPB * ii;
        s->h[(e >> 7) * Y_STR + (e & 127)] = 0.f;
    }
    __syncthreads();

    for (int m = 0; m < PRE_LENN; m++) {
        if (t < BT * 12) {
            int b = t / 12, c = t % 12;
            s->ins[b * 12 + c] = (c < 8)
                ? pre_x[((size_t)m * BATCHN + b0 + b) * 8 + c]
                : pre_y[((size_t)m * BATCHN + b0 + b) * 4 + (c - 8)];
        }
        __syncthreads();
        // gi = in @ W_ih^T + b_ih  (K=12)
        {
            int bg = t & 1, og = t >> 1;
#pragma unroll
            for (int j = 0; j < 3; j++) {
                int o = og * 3 + j;
                const float4* wr = reinterpret_cast<const float4*>(W_ih + (size_t)o * 12);
                float4 w0 = wr[0], w1 = wr[1], w2 = wr[2];
                float w[12] = {w0.x, w0.y, w0.z, w0.w, w1.x, w1.y, w1.z, w1.w,
                               w2.x, w2.y, w2.z, w2.w};
                float bb = s->bih[o];
#pragma unroll
                for (int i = 0; i < 8; i++) {
                    int b = bg + 2 * i;
                    float acc = bb;
#pragma unroll
                    for (int c = 0; c < 12; c++) acc += s->ins[b * 12 + c] * w[c];
                    s->A[b * G_STR + o] = acc;
                }
            }
        }
        // gh = h @ W_hh^T + b_hh
        mm128<3, 0>(g_Whh_r, s->h, Y_STR, s->GH, G_STR, s->bhh);
        __syncthreads();
#pragma unroll
        for (int ii = 0; ii < (BT * HN) / TPB; ii++) {
            int e = t + TPB * ii;
            int b = e >> 7, u = e & 127;
            float r = sigf(s->A[b * G_STR + u]            + s->GH[b * G_STR + u]);
            float z = sigf(s->A[b * G_STR + u + HN]       + s->GH[b * G_STR + u + HN]);
            float n = tanhf(s->A[b * G_STR + u + 2 * HN] + r * s->GH[b * G_STR + u + 2 * HN]);
            float hv = s->h[b * Y_STR + u];
            s->h[b * Y_STR + u] = (1.f - z) * n + z * hv;
        }
        __syncthreads();
    }
#pragma unroll
    for (int ii = 0; ii < (BT * HN) / TPB; ii++) {
        int e = t + TPB * ii;
        int b = e >> 7, u = e & 127;
        g_hn[(size_t)(b0 + b) * HN + u] = s->h[b * Y_STR + u];
    }
}

// ---------------- RK4 ODE + output head ----------------
struct RkS {
    float A [BT * G_STR];     // gi at t0 (then gi at t0+h)
    float B [BT * G_STR];     // gi at t0+h/2
    float GH[BT * G_STR];     // x / gh / z1 scratch
    float y [BT * Y_STR];
    float t1[BT * Y_STR];
    float u [BT * KIN];
    float We[HN * 9];
    float be[HN];
    float bcih[G3N];
    float bchh[G3N];
    float W2[KOUTN * W2_STR];
};

__device__ __forceinline__ void xbuild(RkS* s)
{
    int t = threadIdx.x;
#pragma unroll
    for (int ii = 0; ii < (BT * HN) / TPB; ii++) {
        int e = t + TPB * ii;
        int b = e >> 7, kk = e & 127;
        float acc = s->be[kk];
#pragma unroll
        for (int c = 0; c < KIN; c++) acc += s->u[b * KIN + c] * s->We[kk * 9 + c];
        s->GH[b * G_STR + kk] = tanhf(acc);
    }
}

// STAGE 1..4. gi: stage input-gate table; yy = stage state input.
// ka lives in registers (same thread owns same (b,u) in every stage).
template <int STAGE>
__device__ __forceinline__ void combine(RkS* s, const float* gi, const float* yy,
                                        float* rka)
{
    int t = threadIdx.x;
#pragma unroll
    for (int ii = 0; ii < (BT * HN) / TPB; ii++) {
        int e = t + TPB * ii;
        int b = e >> 7, u = e & 127;
        float r = sigf(gi[b * G_STR + u]           + s->GH[b * G_STR + u]);
        float z = sigf(gi[b * G_STR + u + HN]      + s->GH[b * G_STR + u + HN]);
        float n = tanhf(gi[b * G_STR + u + 2 * HN] + r * s->GH[b * G_STR + u + 2 * HN]);
        float k = (1.f - z) * (n - yy[b * Y_STR + u]) * 10.f;   // /UT
        float yb = s->y[b * Y_STR + u];
        if (STAGE == 1) { rka[ii] = k;           s->t1[b * Y_STR + u] = yb + 0.05f * k; }
        if (STAGE == 2) { rka[ii] += 2.f * k;    s->t1[b * Y_STR + u] = yb + 0.05f * k; }
        if (STAGE == 3) { rka[ii] += 2.f * k;    s->t1[b * Y_STR + u] = yb + 0.1f * k; }
        if (STAGE == 4) { s->y[b * Y_STR + u] = yb + 0.0166666667f * (rka[ii] + k); }
    }
}

__global__ void __launch_bounds__(TPB, 2) rk4_kernel(
    const float* __restrict__ W_e, const float* __restrict__ b_e,
    const float* __restrict__ bc_ih, const float* __restrict__ bc_hh,
    const float* __restrict__ W2,
    float* __restrict__ out)
{
    extern __shared__ char smraw[];
    RkS* s = reinterpret_cast<RkS*>(smraw);
    const int t  = threadIdx.x;
    const int b0 = blockIdx.x * BT;
    float rka[(BT * HN) / TPB];

    // ---- load weights / state into smem ----
    for (int idx = t; idx < HN * KIN; idx += TPB) s->We[(idx >> 3) * 9 + (idx & 7)] = W_e[idx];
    for (int idx = t; idx < HN; idx += TPB) s->be[idx] = b_e[idx];
    for (int idx = t; idx < G3N; idx += TPB) { s->bcih[idx] = bc_ih[idx]; s->bchh[idx] = bc_hh[idx]; }
    for (int idx = t; idx < KOUTN * 2 * HN; idx += TPB)
        s->W2[(idx >> 8) * W2_STR + (idx & 255)] = W2[idx];
#pragma unroll
    for (int ii = 0; ii < (BT * HN) / TPB; ii++) {
        int e = t + TPB * ii;
        int b = e >> 7, u = e & 127;
        s->y[b * Y_STR + u] = g_hn[(size_t)(b0 + b) * HN + u];
    }
    if (t < BT * KIN) {                      // u(t=0) = ys[0]
        int b = t >> 3, c = t & 7;
        s->u[t] = g_ys[(size_t)(b0 + b) * KIN + c];
    }
    __syncthreads();
    xbuild(s);
    __syncthreads();
    mm128<3, 0>(g_Wcih_r, s->GH, G_STR, s->A, G_STR, s->bcih);   // gi(t=0)

    const float cm = 0.000625f;  // 0.375 * h^2 / 6

    for (int i = 0; i < FWD_LENN; i++) {
        __syncthreads();
        if (t < BT * KIN) {                  // u(t0 + h/2) via spline midpoint
            int b = t >> 3, c = t & 7;
            size_t col = (size_t)(b0 + b) * KIN + c;
            float y0 = g_ys[(size_t)i * COLSN + col];
            float y1 = g_ys[(size_t)(i + 1) * COLSN + col];
            float m0 = g_M [(size_t)i * COLSN + col];
            float m1 = g_M [(size_t)(i + 1) * COLSN + col];
            s->u[t] = 0.5f * (y0 + y1) - cm * (m0 + m1);
        }
        __syncthreads();
        xbuild(s);                                              // GH = x_mid
        __syncthreads();
        mm128<3, 0>(g_Wcih_r, s->GH, G_STR, s->B, G_STR, s->bcih); // B = gi_mid
        __syncthreads();
        mm128<3, 0>(g_Wchh_r, s->y, Y_STR, s->GH, G_STR, s->bchh); // gh(y)
        __syncthreads();
        combine<1>(s, s->A, s->y, rka);
        __syncthreads();
        if (t < BT * KIN) {                  // u(t0 + h) = ys[i+1]
            int b = t >> 3, c = t & 7;
            s->u[t] = g_ys[(size_t)(i + 1) * COLSN + (size_t)(b0 + b) * KIN + c];
        }
        __syncthreads();
        xbuild(s);                                              // GH = x_end
        __syncthreads();
        mm128<3, 0>(g_Wcih_r, s->GH, G_STR, s->A, G_STR, s->bcih); // A = gi(t0+h)
        __syncthreads();
        mm128<3, 0>(g_Wchh_r, s->t1, Y_STR, s->GH, G_STR, s->bchh);
        __syncthreads();
        combine<2>(s, s->B, s->t1, rka);
        __syncthreads();
        mm128<3, 0>(g_Wchh_r, s->t1, Y_STR, s->GH, G_STR, s->bchh);
        __syncthreads();
        combine<3>(s, s->B, s->t1, rka);
        __syncthreads();
        mm128<3, 0>(g_Wchh_r, s->t1, Y_STR, s->GH, G_STR, s->bchh);
        __syncthreads();
        combine<4>(s, s->A, s->t1, rka);                        // y updated
        __syncthreads();
        // ---- head: z1 = tanh(y @ W1^T) [BT x 256] into GH ----
        mm128<2, 1>(g_W1_r, s->y, Y_STR, s->GH, G_STR, (const float*)0);
        __syncthreads();
        // out = z1 @ W2^T  [BT x 4]; 256 threads = 64 (b,o) ids x 4 K-parts
        {
            int out_id = t >> 2;      // 0..63
            int part   = t & 3;
            int b = out_id >> 2;      // 0..15
            int o = out_id & 3;
            const float* z = &s->GH[b * G_STR];
            const float* w = &s->W2[o * W2_STR];
            float acc = 0.f;
            int k0 = part * 64;
#pragma unroll 8
            for (int kk = 0; kk < 64; kk++) acc += z[k0 + kk] * w[k0 + kk];
            acc += __shfl_xor_sync(0xffffffffu, acc, 1);
            acc += __shfl_xor_sync(0xffffffffu, acc, 2);
            if (part == 0)
                out[((size_t)i * BATCHN + b0 + b) * KOUTN + o] = acc;
        }
    }
}

extern "C" void kernel_launch(void* const* d_in, const int* in_sizes, int n_in,
                              void* d_out, int out_size)
{
    const float* pre_x  = (const float*)d_in[0];
    const float* pre_y  = (const float*)d_in[1];
    const float* fwd_x  = (const float*)d_in[2];
    const float* W_ih   = (const float*)d_in[3];
    const float* W_hh   = (const float*)d_in[4];
    const float* b_ih   = (const float*)d_in[5];
    const float* b_hh   = (const float*)d_in[6];
    const float* W_e    = (const float*)d_in[7];
    const float* b_e    = (const float*)d_in[8];
    const float* Wc_ih  = (const float*)d_in[9];
    const float* Wc_hh  = (const float*)d_in[10];
    const float* bc_ih  = (const float*)d_in[11];
    const float* bc_hh  = (const float*)d_in[12];
    const float* W1     = (const float*)d_in[13];
    const float* W2     = (const float*)d_in[14];
    float* out = (float*)d_out;

    // Non-stream API: persistent per-function state, legal under graph capture.
    cudaFuncSetAttribute(enc_kernel, cudaFuncAttributeMaxDynamicSharedMemorySize,
                         (int)sizeof(EncS));
    cudaFuncSetAttribute(rk4_kernel, cudaFuncAttributeMaxDynamicSharedMemorySize,
                         (int)sizeof(RkS));

    int fill_n = (FWD_LENN + 1) * COLSN;
    reorder_kernel<<<(32 * 384 + 255) / 256, 256>>>(Wc_ih, Wc_hh, W_hh, W1);
    fill_kernel<<<(fill_n + 255) / 256, 256>>>(pre_x, fwd_x);
    thomas_kernel<<<COLSN / 256, 256>>>();
    enc_kernel<<<NCTA, TPB, sizeof(EncS)>>>(pre_x, pre_y, W_ih, b_ih, b_hh);
    rk4_kernel<<<NCTA, TPB, sizeof(RkS)>>>(W_e, b_e, bc_ih, bc_hh, W2, out);
}

// round 12
// speedup vs baseline: 1.1342x; 1.1342x over previous
#include <cuda_runtime.h>
#include <cuda_bf16.h>

// ---------------- problem constants ----------------
#define BATCHN   4096
#define KIN      8
#define KOUTN    4
#define HN       128
#define G3N      384           // 3*H gates
#define PRE_LENN 64
#define FWD_LENN 128
#define BT       16            // batch rows per CTA (rk4/enc)
#define TPB      256
#define NCTA     (BATCHN/BT)   // 256
#define COLSN    (BATCHN*KIN)  // 32768
#define Y_STR    132           // padded stride for [BT][128] smem buffers
#define G_STR    388           // padded stride for [BT][384] smem buffers
#define Z_STR    260
#define W2_STR   260
#define HT       16            // batch rows per head CTA

// ---------------- device scratch (no allocations allowed) ----------------
__device__ float g_ys[(FWD_LENN + 1) * COLSN];  // spline knots  [129][B][8]
__device__ float g_M [(FWD_LENN + 1) * COLSN];  // spline 2nd derivs
__device__ float g_hn[BATCHN * HN];             // encoder final hidden
__device__ float g_ytraj[(size_t)FWD_LENN * BATCHN * HN];  // y trajectory (268MB)
// reordered weights: idx = k4*(OPT*128) + j*128 + og ; value = W[(og*OPT+j)][4k4..4k4+3]
__device__ float4 g_Wcih_r[32 * 384];
__device__ float4 g_Wchh_r[32 * 384];
__device__ float4 g_Whh_r [32 * 384];
__device__ float4 g_W1_r  [32 * 256];

// ---------------- packed fp32x2 FMA (Blackwell FFMA2; PTX-only path) ----------
#define FMA2(d, a, b) asm("fma.rn.f32x2 %0, %1, %2, %0;" : "+l"(d) : "l"(a), "l"(b))

__device__ __forceinline__ float ull_sum(unsigned long long v) {
    float lo = __uint_as_float((unsigned)(v & 0xffffffffull));
    float hi = __uint_as_float((unsigned)(v >> 32));
    return lo + hi;
}

__device__ __forceinline__ float sigf(float x) { return 1.f / (1.f + __expf(-x)); }

// ---------------- core GEMM: Out[BT x (128*OPT)] = Xs[BT x 128] @ W^T -------
// TPB=256: bg = t&1, og = t>>1. Each thread: OPT outputs x 8 batch rows.
// K paired via f32x2. W for next k4 prefetched before current FMA burst.
// MODE 0: Out = sum + bias[o]; MODE 1: Out = tanh(sum)
template <int OPT, int MODE>
__device__ __forceinline__ void mm128(const float4* __restrict__ Wr,
                                      const float* __restrict__ Xs, int xs,
                                      float* __restrict__ Out, int os,
                                      const float* __restrict__ bias)
{
    const int t  = threadIdx.x;
    const int bg = t & 1;
    const int og = t >> 1;
    unsigned long long acc[OPT][8];
#pragma unroll
    for (int j = 0; j < OPT; j++)
#pragma unroll
        for (int i = 0; i < 8; i++) acc[j][i] = 0ull;

    const float4* wptr = Wr + og;
    unsigned long long wv[OPT][2];
#pragma unroll
    for (int j = 0; j < OPT; j++) {
        ulonglong2 w = *reinterpret_cast<const ulonglong2*>(wptr + j * 128);
        wv[j][0] = w.x; wv[j][1] = w.y;
    }
    wptr += OPT * 128;

#pragma unroll 2
    for (int k4 = 0; k4 < 32; k4++) {
        const int k = k4 * 4;
        // prefetch next k4's W first (longest latency)
        unsigned long long wn[OPT][2];
        if (k4 < 31) {
#pragma unroll
            for (int j = 0; j < OPT; j++) {
                ulonglong2 w = *reinterpret_cast<const ulonglong2*>(wptr + j * 128);
                wn[j][0] = w.x; wn[j][1] = w.y;
            }
            wptr += OPT * 128;
        }
        // two 4-batch halves to bound register pressure
#pragma unroll
        for (int h = 0; h < 2; h++) {
            unsigned long long x01[4], x23[4];
#pragma unroll
            for (int i = 0; i < 4; i++) {
                int b = bg + 2 * (h * 4 + i);
                ulonglong2 xv = *reinterpret_cast<const ulonglong2*>(Xs + b * xs + k);
                x01[i] = xv.x;
                x23[i] = xv.y;
            }
#pragma unroll
            for (int j = 0; j < OPT; j++)
#pragma unroll
                for (int i = 0; i < 4; i++) {
                    FMA2(acc[j][h * 4 + i], wv[j][0], x01[i]);
                    FMA2(acc[j][h * 4 + i], wv[j][1], x23[i]);
                }
        }
#pragma unroll
        for (int j = 0; j < OPT; j++) { wv[j][0] = wn[j][0]; wv[j][1] = wn[j][1]; }
    }
#pragma unroll
    for (int j = 0; j < OPT; j++) {
        int o = og * OPT + j;
#pragma unroll
        for (int i = 0; i < 8; i++) {
            int b = bg + 2 * i;
            float s = ull_sum(acc[j][i]);
            if (MODE == 0) Out[b * os + o] = s + bias[o];
            else           Out[b * os + o] = tanhf(s);
        }
    }
}

// ---------------- weight reorder prep ----------------
__global__ void reorder_kernel(const float* __restrict__ Wc_ih,
                               const float* __restrict__ Wc_hh,
                               const float* __restrict__ W_hh,
                               const float* __restrict__ W1)
{
    int idx = blockIdx.x * blockDim.x + threadIdx.x;
    if (idx < 32 * 384) {
        int k4 = idx / 384, r = idx % 384;
        int j = r >> 7, og = r & 127;
        int row = og * 3 + j;
        g_Wcih_r[idx] = *reinterpret_cast<const float4*>(Wc_ih + (size_t)row * HN + k4 * 4);
        g_Wchh_r[idx] = *reinterpret_cast<const float4*>(Wc_hh + (size_t)row * HN + k4 * 4);
        g_Whh_r [idx] = *reinterpret_cast<const float4*>(W_hh  + (size_t)row * HN + k4 * 4);
    }
    if (idx < 32 * 256) {
        int k4 = idx / 256, r = idx % 256;
        int j = r >> 7, og = r & 127;
        int row = og * 2 + j;
        g_W1_r[idx] = *reinterpret_cast<const float4*>(W1 + (size_t)row * HN + k4 * 4);
    }
}

// ---------------- spline prep ----------------
__global__ void fill_kernel(const float* __restrict__ pre_x, const float* __restrict__ fwd_x)
{
    int e = blockIdx.x * blockDim.x + threadIdx.x;
    if (e >= (FWD_LENN + 1) * COLSN) return;
    int i   = e >> 15;             // COLSN = 2^15
    int col = e & (COLSN - 1);
    g_ys[e] = (i == 0) ? pre_x[(size_t)(PRE_LENN - 1) * COLSN + col]
                       : fwd_x[(size_t)(i - 1) * COLSN + col];
}

// Thomas solve of (1,4,1) tridiagonal per column; M[0]=M[128]=0
__global__ void thomas_kernel()
{
    __shared__ float cp[FWD_LENN];
    int t = threadIdx.x;
    int col = blockIdx.x * blockDim.x + t;
    if (t == 0) {
        cp[0] = 0.25f;
        for (int i = 1; i < FWD_LENN - 1; i++) cp[i] = 1.f / (4.f - cp[i - 1]);
    }
    __syncthreads();
    const float rc = 6.0f / (0.1f * 0.1f);
    float y0 = g_ys[col];
    float y1 = g_ys[COLSN + col];
    float dp = 0.f;
    for (int j = 0; j < FWD_LENN - 1; j++) {          // 127 inner unknowns
        float y2 = g_ys[(size_t)(j + 2) * COLSN + col];
        float rhs = rc * (y0 - 2.f * y1 + y2);
        dp = (rhs - dp) * cp[j];
        g_M[(size_t)(j + 1) * COLSN + col] = dp;
        y0 = y1; y1 = y2;
    }
    float x = dp;                                     // M[127] final
    for (int j = FWD_LENN - 3; j >= 0; j--) {
        float dj = g_M[(size_t)(j + 1) * COLSN + col];
        x = dj - cp[j] * x;
        g_M[(size_t)(j + 1) * COLSN + col] = x;
    }
    g_M[col] = 0.f;
    g_M[(size_t)FWD_LENN * COLSN + col] = 0.f;
}

// ---------------- encoder GRU ----------------
struct EncS {
    float A [BT * G_STR];
    float GH[BT * G_STR];
    float h [BT * Y_STR];
    float ins[BT * 12];
    float bih[G3N];
    float bhh[G3N];
};

__global__ void __launch_bounds__(TPB, 2) enc_kernel(
    const float* __restrict__ pre_x, const float* __restrict__ pre_y,
    const float* __restrict__ W_ih,
    const float* __restrict__ b_ih, const float* __restrict__ b_hh)
{
    extern __shared__ char smraw[];
    EncS* s = reinterpret_cast<EncS*>(smraw);
    const int t  = threadIdx.x;
    const int b0 = blockIdx.x * BT;

    for (int idx = t; idx < G3N; idx += TPB) { s->bih[idx] = b_ih[idx]; s->bhh[idx] = b_hh[idx]; }
#pragma unroll
    for (int ii = 0; ii < (BT * HN) / TPB; ii++) {
        int e = t + TPB * ii;
        s->h[(e >> 7) * Y_STR + (e & 127)] = 0.f;
    }
    __syncthreads();

    for (int m = 0; m < PRE_LENN; m++) {
        if (t < BT * 12) {
            int b = t / 12, c = t % 12;
            s->ins[b * 12 + c] = (c < 8)
                ? pre_x[((size_t)m * BATCHN + b0 + b) * 8 + c]
                : pre_y[((size_t)m * BATCHN + b0 + b) * 4 + (c - 8)];
        }
        __syncthreads();
        // gi = in @ W_ih^T + b_ih  (K=12)
        {
            int bg = t & 1, og = t >> 1;
#pragma unroll
            for (int j = 0; j < 3; j++) {
                int o = og * 3 + j;
                const float4* wr = reinterpret_cast<const float4*>(W_ih + (size_t)o * 12);
                float4 w0 = wr[0], w1 = wr[1], w2 = wr[2];
                float w[12] = {w0.x, w0.y, w0.z, w0.w, w1.x, w1.y, w1.z, w1.w,
                               w2.x, w2.y, w2.z, w2.w};
                float bb = s->bih[o];
#pragma unroll
                for (int i = 0; i < 8; i++) {
                    int b = bg + 2 * i;
                    float acc = bb;
#pragma unroll
                    for (int c = 0; c < 12; c++) acc += s->ins[b * 12 + c] * w[c];
                    s->A[b * G_STR + o] = acc;
                }
            }
        }
        // gh = h @ W_hh^T + b_hh
        mm128<3, 0>(g_Whh_r, s->h, Y_STR, s->GH, G_STR, s->bhh);
        __syncthreads();
#pragma unroll
        for (int ii = 0; ii < (BT * HN) / TPB; ii++) {
            int e = t + TPB * ii;
            int b = e >> 7, u = e & 127;
            float r = sigf(s->A[b * G_STR + u]            + s->GH[b * G_STR + u]);
            float z = sigf(s->A[b * G_STR + u + HN]       + s->GH[b * G_STR + u + HN]);
            float n = tanhf(s->A[b * G_STR + u + 2 * HN] + r * s->GH[b * G_STR + u + 2 * HN]);
            float hv = s->h[b * Y_STR + u];
            s->h[b * Y_STR + u] = (1.f - z) * n + z * hv;
        }
        __syncthreads();
    }
#pragma unroll
    for (int ii = 0; ii < (BT * HN) / TPB; ii++) {
        int e = t + TPB * ii;
        int b = e >> 7, u = e & 127;
        g_hn[(size_t)(b0 + b) * HN + u] = s->h[b * Y_STR + u];
    }
}

// ---------------- RK4 ODE (head deferred) ----------------
struct RkS {
    float A [BT * G_STR];     // gi at t0 (then gi at t0+h)
    float B [BT * G_STR];     // gi at t0+h/2
    float GH[BT * G_STR];     // x / gh scratch
    float y [BT * Y_STR];
    float t1[BT * Y_STR];
    float u [BT * KIN];
    float We[HN * 9];
    float be[HN];
    float bcih[G3N];
    float bchh[G3N];
};

__device__ __forceinline__ void xbuild(RkS* s)
{
    int t = threadIdx.x;
#pragma unroll
    for (int ii = 0; ii < (BT * HN) / TPB; ii++) {
        int e = t + TPB * ii;
        int b = e >> 7, kk = e & 127;
        float acc = s->be[kk];
#pragma unroll
        for (int c = 0; c < KIN; c++) acc += s->u[b * KIN + c] * s->We[kk * 9 + c];
        s->GH[b * G_STR + kk] = tanhf(acc);
    }
}

// STAGE 1..4. gi: stage input-gate table; yy = stage state input.
// ka in registers. Stage 4 also streams y to the trajectory buffer.
template <int STAGE>
__device__ __forceinline__ void combine(RkS* s, const float* gi, const float* yy,
                                        float* rka, float* ytr)
{
    int t = threadIdx.x;
#pragma unroll
    for (int ii = 0; ii < (BT * HN) / TPB; ii++) {
        int e = t + TPB * ii;
        int b = e >> 7, u = e & 127;
        float r = sigf(gi[b * G_STR + u]           + s->GH[b * G_STR + u]);
        float z = sigf(gi[b * G_STR + u + HN]      + s->GH[b * G_STR + u + HN]);
        float n = tanhf(gi[b * G_STR + u + 2 * HN] + r * s->GH[b * G_STR + u + 2 * HN]);
        float k = (1.f - z) * (n - yy[b * Y_STR + u]) * 10.f;   // /UT
        float yb = s->y[b * Y_STR + u];
        if (STAGE == 1) { rka[ii] = k;           s->t1[b * Y_STR + u] = yb + 0.05f * k; }
        if (STAGE == 2) { rka[ii] += 2.f * k;    s->t1[b * Y_STR + u] = yb + 0.05f * k; }
        if (STAGE == 3) { rka[ii] += 2.f * k;    s->t1[b * Y_STR + u] = yb + 0.1f * k; }
        if (STAGE == 4) {
            float yn = yb + 0.0166666667f * (rka[ii] + k);
            s->y[b * Y_STR + u] = yn;
            ytr[(size_t)b * HN + u] = yn;
        }
    }
}

__global__ void __launch_bounds__(TPB, 2) rk4_kernel(
    const float* __restrict__ W_e, const float* __restrict__ b_e,
    const float* __restrict__ bc_ih, const float* __restrict__ bc_hh)
{
    extern __shared__ char smraw[];
    RkS* s = reinterpret_cast<RkS*>(smraw);
    const int t  = threadIdx.x;
    const int b0 = blockIdx.x * BT;
    float rka[(BT * HN) / TPB];

    // ---- load weights / state into smem ----
    for (int idx = t; idx < HN * KIN; idx += TPB) s->We[(idx >> 3) * 9 + (idx & 7)] = W_e[idx];
    for (int idx = t; idx < HN; idx += TPB) s->be[idx] = b_e[idx];
    for (int idx = t; idx < G3N; idx += TPB) { s->bcih[idx] = bc_ih[idx]; s->bchh[idx] = bc_hh[idx]; }
#pragma unroll
    for (int ii = 0; ii < (BT * HN) / TPB; ii++) {
        int e = t + TPB * ii;
        int b = e >> 7, u = e & 127;
        s->y[b * Y_STR + u] = g_hn[(size_t)(b0 + b) * HN + u];
    }
    if (t < BT * KIN) {                      // u(t=0) = ys[0]
        int b = t >> 3, c = t & 7;
        s->u[t] = g_ys[(size_t)(b0 + b) * KIN + c];
    }
    __syncthreads();
    xbuild(s);
    __syncthreads();
    mm128<3, 0>(g_Wcih_r, s->GH, G_STR, s->A, G_STR, s->bcih);   // gi(t=0)

    const float cm = 0.000625f;  // 0.375 * h^2 / 6

    for (int i = 0; i < FWD_LENN; i++) {
        float* ytr = g_ytraj + ((size_t)i * BATCHN + b0) * HN;
        __syncthreads();
        if (t < BT * KIN) {                  // u(t0 + h/2) via spline midpoint
            int b = t >> 3, c = t & 7;
            size_t col = (size_t)(b0 + b) * KIN + c;
            float y0 = g_ys[(size_t)i * COLSN + col];
            float y1 = g_ys[(size_t)(i + 1) * COLSN + col];
            float m0 = g_M [(size_t)i * COLSN + col];
            float m1 = g_M [(size_t)(i + 1) * COLSN + col];
            s->u[t] = 0.5f * (y0 + y1) - cm * (m0 + m1);
        }
        __syncthreads();
        xbuild(s);                                              // GH = x_mid
        __syncthreads();
        mm128<3, 0>(g_Wcih_r, s->GH, G_STR, s->B, G_STR, s->bcih); // B = gi_mid
        __syncthreads();
        mm128<3, 0>(g_Wchh_r, s->y, Y_STR, s->GH, G_STR, s->bchh); // gh(y)
        __syncthreads();
        combine<1>(s, s->A, s->y, rka, ytr);
        __syncthreads();
        if (t < BT * KIN) {                  // u(t0 + h) = ys[i+1]
            int b = t >> 3, c = t & 7;
            s->u[t] = g_ys[(size_t)(i + 1) * COLSN + (size_t)(b0 + b) * KIN + c];
        }
        __syncthreads();
        xbuild(s);                                              // GH = x_end
        __syncthreads();
        mm128<3, 0>(g_Wcih_r, s->GH, G_STR, s->A, G_STR, s->bcih); // A = gi(t0+h)
        __syncthreads();
        mm128<3, 0>(g_Wchh_r, s->t1, Y_STR, s->GH, G_STR, s->bchh);
        __syncthreads();
        combine<2>(s, s->B, s->t1, rka, ytr);
        __syncthreads();
        mm128<3, 0>(g_Wchh_r, s->t1, Y_STR, s->GH, G_STR, s->bchh);
        __syncthreads();
        combine<3>(s, s->B, s->t1, rka, ytr);
        __syncthreads();
        mm128<3, 0>(g_Wchh_r, s->t1, Y_STR, s->GH, G_STR, s->bchh);
        __syncthreads();
        combine<4>(s, s->A, s->t1, rka, ytr);                   // y updated + streamed
    }
}

// ---------------- output head (parallel over all steps) ----------------
__global__ void __launch_bounds__(TPB, 2) head_kernel(
    const float* __restrict__ W2, float* __restrict__ out)
{
    __shared__ float ys [HT * Y_STR];
    __shared__ float z1 [HT * Z_STR];
    __shared__ float w2s[KOUTN * W2_STR];
    const int t  = threadIdx.x;
    const int b0 = blockIdx.x * HT;
    const int i  = blockIdx.y;

    for (int idx = t; idx < KOUTN * 2 * HN; idx += TPB)
        w2s[(idx >> 8) * W2_STR + (idx & 255)] = W2[idx];
    {
        const float4* src = reinterpret_cast<const float4*>(
            g_ytraj + ((size_t)i * BATCHN + b0) * HN);
#pragma unroll
        for (int ii = 0; ii < (HT * HN / 4) / TPB; ii++) {
            int e = t + TPB * ii;               // float4 index
            int b = e >> 5, u4 = e & 31;        // 32 float4 per row
            *reinterpret_cast<float4*>(&ys[b * Y_STR + u4 * 4]) = src[e];
        }
    }
    __syncthreads();
    mm128<2, 1>(g_W1_r, ys, Y_STR, z1, Z_STR, (const float*)0);  // z1 = tanh(y@W1^T)
    __syncthreads();
    {
        int out_id = t >> 2;      // 0..63
        int part   = t & 3;
        int b = out_id >> 2;      // 0..15
        int o = out_id & 3;
        const float* z = &z1[b * Z_STR];
        const float* w = &w2s[o * W2_STR];
        float acc = 0.f;
#pragma unroll 8
        for (int kk = 0; kk < 64; kk++) acc += z[part + 4 * kk] * w[part + 4 * kk];
        acc += __shfl_xor_sync(0xffffffffu, acc, 1);
        acc += __shfl_xor_sync(0xffffffffu, acc, 2);
        if (part == 0)
            out[((size_t)i * BATCHN + b0 + b) * KOUTN + o] = acc;
    }
}

extern "C" void kernel_launch(void* const* d_in, const int* in_sizes, int n_in,
                              void* d_out, int out_size)
{
    const float* pre_x  = (const float*)d_in[0];
    const float* pre_y  = (const float*)d_in[1];
    const float* fwd_x  = (const float*)d_in[2];
    const float* W_ih   = (const float*)d_in[3];
    const float* W_hh   = (const float*)d_in[4];
    const float* b_ih   = (const float*)d_in[5];
    const float* b_hh   = (const float*)d_in[6];
    const float* W_e    = (const float*)d_in[7];
    const float* b_e    = (const float*)d_in[8];
    const float* Wc_ih  = (const float*)d_in[9];
    const float* Wc_hh  = (const float*)d_in[10];
    const float* bc_ih  = (const float*)d_in[11];
    const float* bc_hh  = (const float*)d_in[12];
    const float* W1     = (const float*)d_in[13];
    const float* W2     = (const float*)d_in[14];
    float* out = (float*)d_out;

    // Non-stream API: persistent per-function state, legal under graph capture.
    cudaFuncSetAttribute(enc_kernel, cudaFuncAttributeMaxDynamicSharedMemorySize,
                         (int)sizeof(EncS));
    cudaFuncSetAttribute(rk4_kernel, cudaFuncAttributeMaxDynamicSharedMemorySize,
                         (int)sizeof(RkS));

    int fill_n = (FWD_LENN + 1) * COLSN;
    reorder_kernel<<<(32 * 384 + 255) / 256, 256>>>(Wc_ih, Wc_hh, W_hh, W1);
    fill_kernel<<<(fill_n + 255) / 256, 256>>>(pre_x, fwd_x);
    thomas_kernel<<<COLSN / 256, 256>>>();
    enc_kernel<<<NCTA, TPB, sizeof(EncS)>>>(pre_x, pre_y, W_ih, b_ih, b_hh);
    rk4_kernel<<<NCTA, TPB, sizeof(RkS)>>>(W_e, b_e, bc_ih, bc_hh);
    dim3 hgrid(BATCHN / HT, FWD_LENN);
    head_kernel<<<hgrid, TPB>>>(W2, out);
}